// round 14
// baseline (speedup 1.0000x reference)
#include <cuda_runtime.h>
#include <cuda_fp16.h>
#include <math.h>

// Problem constants
#define BB 2
#define VV 180
#define RR 32
#define CC 512
#define NPIX 512
#define NROWS (BB*VV*RR)        // 11520
#define NQUADS (NROWS/4)        // 2880
#define PADL 107
#define NPADE 724               // padded entries per row
#define PI_D 3.14159265358979323846
#define MAGICF 12582912.0f      // 1.5*2^23
#define KCONST 362.0f           // 255.5 + PADL - 0.5
#define BUFB  (NPADE * 16)      // bytes per quad-row buffer (11584)

// ---------------- device globals (scratch; no runtime allocation allowed) ----------------
// quad-interleaved padded rows: 16B entry = (mid2(r0,r1), d2(r0,r1), mid2(r2,r3), d2(r2,r3))
__device__ __align__(16) uint4 g_quad[(size_t)NQUADS * NPADE];   // ~33MB

// ---------------- filter: closed-form Ram-Lak, parity-split conv, 8-wide blocking ------
__global__ void __launch_bounds__(256) filter_kernel(const float* __restrict__ sino) {
    __shared__ __align__(16) float sE[4][512];
    __shared__ __align__(16) float sO[4][512];
    __shared__ __align__(16) float sh[256];
    __shared__ __align__(16) float sF[4][512];

    int quad = blockIdx.x;
    int tid  = threadIdx.x;

    for (int i = tid; i < 512; i += 256) {
        int g  = i >> 7;
        int lt = i & 127;
        const float4* rp = (const float4*)(sino + (size_t)(quad * 4 + g) * CC);
        float4 rv = rp[lt];
        int e0i = lt * 2;
        *(float2*)&sE[g][e0i]       = make_float2(rv.x, rv.z);
        *(float2*)&sE[g][e0i + 256] = make_float2(rv.x, rv.z);
        *(float2*)&sO[g][e0i]       = make_float2(rv.y, rv.w);
        *(float2*)&sO[g][e0i + 256] = make_float2(rv.y, rv.w);
    }
    {
        float s = sinf((float)(2 * tid + 1) * (float)(PI_D / 512.0));
        sh[tid] = -7.62939453125e-6f / (s * s);    // -(2/512^2)/sin^2
    }
    __syncthreads();

    int g  = tid >> 6;
    int p  = (tid >> 5) & 1;
    int q  = tid & 31;
    int o0 = q * 8;

    const float* part = p ? sE[g] : sO[g];
    const float* own  = p ? sO[g] : sE[g];

    float a0=0.f,a1=0.f,a2=0.f,a3=0.f,a4=0.f,a5=0.f,a6=0.f,a7=0.f;
    float4 B4 = *(const float4*)&part[o0 + 256];
    float4 C4 = *(const float4*)&part[o0 + 260];
    if (p == 0) {
        #pragma unroll 4
        for (int k0 = 0; k0 < 256; k0 += 4) {
            float4 hv = *(const float4*)&sh[k0];
            float4 A4 = *(const float4*)&part[o0 - k0 + 252];
            a0 = fmaf(hv.x, A4.w, a0); a0 = fmaf(hv.y, A4.z, a0); a0 = fmaf(hv.z, A4.y, a0); a0 = fmaf(hv.w, A4.x, a0);
            a1 = fmaf(hv.x, B4.x, a1); a1 = fmaf(hv.y, A4.w, a1); a1 = fmaf(hv.z, A4.z, a1); a1 = fmaf(hv.w, A4.y, a1);
            a2 = fmaf(hv.x, B4.y, a2); a2 = fmaf(hv.y, B4.x, a2); a2 = fmaf(hv.z, A4.w, a2); a2 = fmaf(hv.w, A4.z, a2);
            a3 = fmaf(hv.x, B4.z, a3); a3 = fmaf(hv.y, B4.y, a3); a3 = fmaf(hv.z, B4.x, a3); a3 = fmaf(hv.w, A4.w, a3);
            a4 = fmaf(hv.x, B4.w, a4); a4 = fmaf(hv.y, B4.z, a4); a4 = fmaf(hv.z, B4.y, a4); a4 = fmaf(hv.w, B4.x, a4);
            a5 = fmaf(hv.x, C4.x, a5); a5 = fmaf(hv.y, B4.w, a5); a5 = fmaf(hv.z, B4.z, a5); a5 = fmaf(hv.w, B4.y, a5);
            a6 = fmaf(hv.x, C4.y, a6); a6 = fmaf(hv.y, C4.x, a6); a6 = fmaf(hv.z, B4.w, a6); a6 = fmaf(hv.w, B4.z, a6);
            a7 = fmaf(hv.x, C4.z, a7); a7 = fmaf(hv.y, C4.y, a7); a7 = fmaf(hv.z, C4.x, a7); a7 = fmaf(hv.w, B4.w, a7);
            C4 = B4; B4 = A4;
        }
    } else {
        #pragma unroll 4
        for (int k0 = 0; k0 < 256; k0 += 4) {
            float4 hv = *(const float4*)&sh[k0];
            float4 A4 = *(const float4*)&part[o0 - k0 + 252];
            a0 = fmaf(hv.x, B4.x, a0); a0 = fmaf(hv.y, A4.w, a0); a0 = fmaf(hv.z, A4.z, a0); a0 = fmaf(hv.w, A4.y, a0);
            a1 = fmaf(hv.x, B4.y, a1); a1 = fmaf(hv.y, B4.x, a1); a1 = fmaf(hv.z, A4.w, a1); a1 = fmaf(hv.w, A4.z, a1);
            a2 = fmaf(hv.x, B4.z, a2); a2 = fmaf(hv.y, B4.y, a2); a2 = fmaf(hv.z, B4.x, a2); a2 = fmaf(hv.w, A4.w, a2);
            a3 = fmaf(hv.x, B4.w, a3); a3 = fmaf(hv.y, B4.z, a3); a3 = fmaf(hv.z, B4.y, a3); a3 = fmaf(hv.w, B4.x, a3);
            a4 = fmaf(hv.x, C4.x, a4); a4 = fmaf(hv.y, B4.w, a4); a4 = fmaf(hv.z, B4.z, a4); a4 = fmaf(hv.w, B4.y, a4);
            a5 = fmaf(hv.x, C4.y, a5); a5 = fmaf(hv.y, C4.x, a5); a5 = fmaf(hv.z, B4.w, a5); a5 = fmaf(hv.w, B4.z, a5);
            a6 = fmaf(hv.x, C4.z, a6); a6 = fmaf(hv.y, C4.y, a6); a6 = fmaf(hv.z, C4.x, a6); a6 = fmaf(hv.w, B4.w, a6);
            a7 = fmaf(hv.x, C4.w, a7); a7 = fmaf(hv.y, C4.z, a7); a7 = fmaf(hv.z, C4.y, a7); a7 = fmaf(hv.w, C4.x, a7);
            C4 = B4; B4 = A4;
        }
    }
    int ob = 2 * o0 + p;
    sF[g][ob + 0]  = fmaf(0.5f, own[o0 + 0], a0);
    sF[g][ob + 2]  = fmaf(0.5f, own[o0 + 1], a1);
    sF[g][ob + 4]  = fmaf(0.5f, own[o0 + 2], a2);
    sF[g][ob + 6]  = fmaf(0.5f, own[o0 + 3], a3);
    sF[g][ob + 8]  = fmaf(0.5f, own[o0 + 4], a4);
    sF[g][ob + 10] = fmaf(0.5f, own[o0 + 5], a5);
    sF[g][ob + 12] = fmaf(0.5f, own[o0 + 6], a6);
    sF[g][ob + 14] = fmaf(0.5f, own[o0 + 7], a7);
    __syncthreads();

    uint4* dst = g_quad + (size_t)quad * NPADE;
    for (int j = tid; j < NPADE; j += 256) {
        int ia = j - PADL;       ia = ia < 0 ? 0 : (ia > 511 ? 511 : ia);
        int ib = j - (PADL - 1); ib = ib < 0 ? 0 : (ib > 511 ? 511 : ib);
        float f0a = sF[0][ia], f0b = sF[0][ib];
        float f1a = sF[1][ia], f1b = sF[1][ib];
        float f2a = sF[2][ia], f2b = sF[2][ib];
        float f3a = sF[3][ia], f3b = sF[3][ib];
        __half2 m01 = __floats2half2_rn(0.5f * (f0a + f0b), 0.5f * (f1a + f1b));
        __half2 d01 = __floats2half2_rn(f0b - f0a, f1b - f1a);
        __half2 m23 = __floats2half2_rn(0.5f * (f2a + f2b), 0.5f * (f3a + f3b));
        __half2 d23 = __floats2half2_rn(f2b - f2a, f3b - f3a);
        uint4 e;
        e.x = *(unsigned int*)&m01; e.y = *(unsigned int*)&d01;
        e.z = *(unsigned int*)&m23; e.w = *(unsigned int*)&d23;
        dst[j] = e;
    }
}

// ---------------- cp.async helpers ------------------------------------------------------
__device__ __forceinline__ void cp16(unsigned int sdst, const void* gsrc) {
    asm volatile("cp.async.cg.shared.global [%0], [%1], 16;" :: "r"(sdst), "l"(gsrc));
}
__device__ __forceinline__ void cp_commit() { asm volatile("cp.async.commit_group;"); }
__device__ __forceinline__ void cp_wait1()  { asm volatile("cp.async.wait_group 1;"); }
__device__ __forceinline__ void cp_wait0()  { asm volatile("cp.async.wait_group 0;"); }

// ---------------- backprojection: mirror-angle sharing, 1024-thread 16-y blocks ---------
// 512 blocks x 1024 threads. Block = (b, quad rq, 16-y slab); tid = jh*256 + xh,
// jh in 0..3 selects a 4-y strip; thread owns pixel pair (xh, 511-xh) for 4 y's, 4 r's.
// Groups g=0..88: rows v=g+1, vm=179-g; t_vm(x)=t_v(-x). Same inner loop as the 481us
// config; staging bytes HALVED (512 blocks instead of 1024 re-stage the 180 quad rows).
__global__ void __launch_bounds__(1024, 1) bp_kernel(float* __restrict__ out) {
    __shared__ __align__(16) uint4 sbuf[4][NPADE];   // 4 quad-row buffers, 46.3KB
    __shared__ float2 scs[90];

    int tid  = threadIdx.x;
    int blk  = blockIdx.x;
    int slab = blk & 31;              // 32 slabs of 16 y
    int rq   = (blk >> 5) & 7;        // 8 quads
    int b    = blk >> 8;

    if (tid < 90) {
        float th = (float)((double)tid * (PI_D / (double)VV));
        float s, c;
        sincosf(th, &s, &c);
        scs[tid] = make_float2(c, s);
    }

    int xh = tid & 255;
    int jh = tid >> 8;                // 0..3

    unsigned int sb32;
    asm("{ .reg .u64 t; cvta.to.shared.u64 t, %1; cvt.u32.u64 %0, t; }"
        : "=r"(sb32) : "l"((void*)&sbuf[0][0]));
    unsigned int cb = sb32 - 0xB4000000u;    // gather: addr = bits(ts)*16 + cb + buf*BUFB

    const size_t rstr = (size_t)8 * NPADE;   // uint4 per row step
    const uint4* gq = g_quad + ((size_t)(b * VV) * 8 + rq) * NPADE;

    // stage rows (rA, rB) into buffer pair p (bufs 2p, 2p+1); 724 threads, 2 cp each
    auto stage = [&](int rA, int rB, int p) {
        if (tid < NPADE) {
            const uint4* sA = gq + (size_t)rA * rstr;
            const uint4* sB = gq + (size_t)rB * rstr;
            unsigned int dA = sb32 + (unsigned int)(2 * p) * BUFB + tid * 16u;
            cp16(dA, sA + tid);
            cp16(dA + BUFB, sB + tid);
        }
    };

    // prologue: group0 (rows 1,179) -> pair0 ; group1 (rows 2,178) -> pair1
    stage(1, 179, 0); cp_commit();
    stage(2, 178, 1); cp_commit();

    float xp = (float)xh - 255.5f;
    float yb = (float)(slab * 16 + jh * 4) - 255.5f;

    float accA[4][4], accB[4][4];     // [r][j]
    #pragma unroll
    for (int r = 0; r < 4; r++)
        #pragma unroll
        for (int j = 0; j < 4; j++) { accA[r][j] = 0.f; accB[r][j] = 0.f; }

    __half2 hA01[4], hA23[4], hB01[4], hB23[4];
    #pragma unroll
    for (int j = 0; j < 4; j++) {
        hA01[j] = __float2half2_rn(0.f); hA23[j] = __float2half2_rn(0.f);
        hB01[j] = __float2half2_rn(0.f); hB23[j] = __float2half2_rn(0.f);
    }

    for (int g = 0; g < 89; g++) {
        cp_wait1();
        __syncthreads();

        int p = g & 1;
        unsigned int cbV = cb + (unsigned int)(2 * p) * BUFB;
        float2 cs = scs[g + 1];
        float u   = xp * cs.x;
        float w00 = fmaf(yb, cs.y, KCONST);
        float tA0 = __fadd_rn(w00, u);
        float tB0 = __fadd_rn(w00, -u);

        #pragma unroll
        for (int j = 0; j < 4; j++) {
            float tA = fmaf((float)j, cs.y, tA0);
            float tB = fmaf((float)j, cs.y, tB0);
            float tsA  = __fadd_rn(tA, MAGICF);
            float i0A  = __fadd_rn(tsA, -MAGICF);
            float wA   = __fadd_rn(tA, -i0A);
            float tsB  = __fadd_rn(tB, MAGICF);
            float i0B  = __fadd_rn(tsB, -MAGICF);
            float wB   = __fadd_rn(tB, -i0B);
            unsigned int uA = __float_as_uint(tsA) * 16u + cbV;
            unsigned int uB = __float_as_uint(tsB) * 16u + cbV;
            unsigned int wAb, wBb;
            asm("cvt.rn.f16x2.f32 %0, %1, %1;" : "=r"(wAb) : "f"(wA));
            asm("cvt.rn.f16x2.f32 %0, %1, %1;" : "=r"(wBb) : "f"(wB));
            __half2 wA2 = *(__half2*)&wAb, wB2 = *(__half2*)&wBb;

            unsigned int x0, x1, x2, x3;
            // row V @ A
            asm("ld.shared.v4.b32 {%0,%1,%2,%3}, [%4];"
                : "=r"(x0), "=r"(x1), "=r"(x2), "=r"(x3) : "r"(uA));
            hA01[j] = __hadd2(hA01[j], __hfma2(wA2, *(__half2*)&x1, *(__half2*)&x0));
            hA23[j] = __hadd2(hA23[j], __hfma2(wA2, *(__half2*)&x3, *(__half2*)&x2));
            // row V @ B
            asm("ld.shared.v4.b32 {%0,%1,%2,%3}, [%4];"
                : "=r"(x0), "=r"(x1), "=r"(x2), "=r"(x3) : "r"(uB));
            hB01[j] = __hadd2(hB01[j], __hfma2(wB2, *(__half2*)&x1, *(__half2*)&x0));
            hB23[j] = __hadd2(hB23[j], __hfma2(wB2, *(__half2*)&x3, *(__half2*)&x2));
            // row VM @ B -> pixel A  (immediate +BUFB)
            asm("ld.shared.v4.b32 {%0,%1,%2,%3}, [%4+11584];"
                : "=r"(x0), "=r"(x1), "=r"(x2), "=r"(x3) : "r"(uB));
            hA01[j] = __hadd2(hA01[j], __hfma2(wB2, *(__half2*)&x1, *(__half2*)&x0));
            hA23[j] = __hadd2(hA23[j], __hfma2(wB2, *(__half2*)&x3, *(__half2*)&x2));
            // row VM @ A -> pixel B
            asm("ld.shared.v4.b32 {%0,%1,%2,%3}, [%4+11584];"
                : "=r"(x0), "=r"(x1), "=r"(x2), "=r"(x3) : "r"(uA));
            hB01[j] = __hadd2(hB01[j], __hfma2(wA2, *(__half2*)&x1, *(__half2*)&x0));
            hB23[j] = __hadd2(hB23[j], __hfma2(wA2, *(__half2*)&x3, *(__half2*)&x2));
        }

        __syncthreads();
        // stage group g+2 into pair g&1 (rows g+3, 177-g); group 89 = specials (0, 90)
        if (g + 2 <= 88)      stage(g + 3, 177 - g, p);
        else if (g + 2 == 89) stage(0, 90, p);
        cp_commit();

        // flush chunk every 4 groups
        if ((g & 3) == 3) {
            #pragma unroll
            for (int j = 0; j < 4; j++) {
                accA[0][j] += __low2float(hA01[j]);  accA[1][j] += __high2float(hA01[j]);
                accA[2][j] += __low2float(hA23[j]);  accA[3][j] += __high2float(hA23[j]);
                accB[0][j] += __low2float(hB01[j]);  accB[1][j] += __high2float(hB01[j]);
                accB[2][j] += __low2float(hB23[j]);  accB[3][j] += __high2float(hB23[j]);
                hA01[j] = __float2half2_rn(0.f); hA23[j] = __float2half2_rn(0.f);
                hB01[j] = __float2half2_rn(0.f); hB23[j] = __float2half2_rn(0.f);
            }
        }
    }

    // epilogue: specials row0 (buf2) and row90 (buf3) -- staged into pair 1
    cp_wait0();
    __syncthreads();
    {
        unsigned int cb0 = cb + 2u * BUFB;
        // row 0: t' = +-xp + K, y-independent
        {
            float tA = __fadd_rn(KCONST, xp);
            float tsA = __fadd_rn(tA, MAGICF);
            float wA  = __fadd_rn(tA, -__fadd_rn(tsA, -MAGICF));
            float tB = __fadd_rn(KCONST, -xp);
            float tsB = __fadd_rn(tB, MAGICF);
            float wB  = __fadd_rn(tB, -__fadd_rn(tsB, -MAGICF));
            unsigned int wAb, wBb;
            asm("cvt.rn.f16x2.f32 %0, %1, %1;" : "=r"(wAb) : "f"(wA));
            asm("cvt.rn.f16x2.f32 %0, %1, %1;" : "=r"(wBb) : "f"(wB));
            unsigned int x0, x1, x2, x3;
            asm("ld.shared.v4.b32 {%0,%1,%2,%3}, [%4];"
                : "=r"(x0), "=r"(x1), "=r"(x2), "=r"(x3) : "r"(__float_as_uint(tsA) * 16u + cb0));
            __half2 vA01 = __hfma2(*(__half2*)&wAb, *(__half2*)&x1, *(__half2*)&x0);
            __half2 vA23 = __hfma2(*(__half2*)&wAb, *(__half2*)&x3, *(__half2*)&x2);
            asm("ld.shared.v4.b32 {%0,%1,%2,%3}, [%4];"
                : "=r"(x0), "=r"(x1), "=r"(x2), "=r"(x3) : "r"(__float_as_uint(tsB) * 16u + cb0));
            __half2 vB01 = __hfma2(*(__half2*)&wBb, *(__half2*)&x1, *(__half2*)&x0);
            __half2 vB23 = __hfma2(*(__half2*)&wBb, *(__half2*)&x3, *(__half2*)&x2);
            #pragma unroll
            for (int j = 0; j < 4; j++) {
                hA01[j] = __hadd2(hA01[j], vA01); hA23[j] = __hadd2(hA23[j], vA23);
                hB01[j] = __hadd2(hB01[j], vB01); hB23[j] = __hadd2(hB23[j], vB23);
            }
        }
        // row 90: t' = yb + j + K, x-independent -> same contribution to A and B
        #pragma unroll
        for (int j = 0; j < 4; j++) {
            float t  = __fadd_rn(__fadd_rn(yb, (float)j), KCONST);
            float ts = __fadd_rn(t, MAGICF);
            float w  = __fadd_rn(t, -__fadd_rn(ts, -MAGICF));
            unsigned int wb;
            asm("cvt.rn.f16x2.f32 %0, %1, %1;" : "=r"(wb) : "f"(w));
            unsigned int x0, x1, x2, x3;
            asm("ld.shared.v4.b32 {%0,%1,%2,%3}, [%4+11584];"
                : "=r"(x0), "=r"(x1), "=r"(x2), "=r"(x3) : "r"(__float_as_uint(ts) * 16u + cb0));
            __half2 v01 = __hfma2(*(__half2*)&wb, *(__half2*)&x1, *(__half2*)&x0);
            __half2 v23 = __hfma2(*(__half2*)&wb, *(__half2*)&x3, *(__half2*)&x2);
            hA01[j] = __hadd2(hA01[j], v01); hA23[j] = __hadd2(hA23[j], v23);
            hB01[j] = __hadd2(hB01[j], v01); hB23[j] = __hadd2(hB23[j], v23);
        }
        #pragma unroll
        for (int j = 0; j < 4; j++) {
            accA[0][j] += __low2float(hA01[j]);  accA[1][j] += __high2float(hA01[j]);
            accA[2][j] += __low2float(hA23[j]);  accA[3][j] += __high2float(hA23[j]);
            accB[0][j] += __low2float(hB01[j]);  accB[1][j] += __high2float(hB01[j]);
            accB[2][j] += __low2float(hB23[j]);  accB[3][j] += __high2float(hB23[j]);
        }
    }

    const float scale = (float)(PI_D / (double)VV);
    int y0 = slab * 16 + jh * 4;
    #pragma unroll
    for (int r = 0; r < 4; r++) {
        size_t obase = (((size_t)(b * RR + rq * 4 + r)) * NPIX + y0) * NPIX;
        #pragma unroll
        for (int j = 0; j < 4; j++) {
            float vA = accA[r][j] * scale;
            float vB = accB[r][j] * scale;
            out[obase + (size_t)j * NPIX + xh]         = vA > 0.f ? vA : 0.f;
            out[obase + (size_t)j * NPIX + (511 - xh)] = vB > 0.f ? vB : 0.f;
        }
    }
}

// ---------------- launch ----------------------------------------------------------------
extern "C" void kernel_launch(void* const* d_in, const int* in_sizes, int n_in,
                              void* d_out, int out_size) {
    const float* sino = (const float*)d_in[0];
    float* out = (float*)d_out;
    (void)in_sizes; (void)n_in; (void)out_size;

    filter_kernel<<<NQUADS, 256>>>(sino);
    bp_kernel<<<BB * 8 * 32, 1024>>>(out);
}

// round 15
// speedup vs baseline: 1.1858x; 1.1858x over previous
#include <cuda_runtime.h>
#include <cuda_fp16.h>
#include <math.h>

// Problem constants
#define BB 2
#define VV 180
#define RR 32
#define CC 512
#define NPIX 512
#define NROWS (BB*VV*RR)        // 11520
#define NQUADS (NROWS/4)        // 2880
#define PADL 107
#define NPADE 724               // padded entries per row
#define PI_D 3.14159265358979323846
#define MAGICF 12582912.0f      // 1.5*2^23
#define KCONST 362.0f           // 255.5 + PADL - 0.5
#define BUFB  (NPADE * 16)      // bytes per quad-row buffer (11584)

// ---------------- device globals (scratch; no runtime allocation allowed) ----------------
// quad-interleaved padded rows: 16B entry = (mid2(r0,r1), d2(r0,r1), mid2(r2,r3), d2(r2,r3))
__device__ __align__(16) uint4 g_quad[(size_t)NQUADS * NPADE];   // ~33MB

// ---------------- filter: truncated Ram-Lak (|j|<=127 + circular mirror), parity conv --
// h[0]=1/2, h[even]=0, h[odd j]=-(2/N^2)/sin^2(pi j/N). Taps for odd |j| in (127,385)
// are <=1.5e-5 and truncated (adds ~2e-4 rel err, halves FMA work).
// k0 in [0,64) covers j=1..127; k0 in [192,256) covers the wrap side j=385..511.
__global__ void __launch_bounds__(256) filter_kernel(const float* __restrict__ sino) {
    __shared__ __align__(16) float sE[4][512];
    __shared__ __align__(16) float sO[4][512];
    __shared__ __align__(16) float sh[256];
    __shared__ __align__(16) float sF[4][512];

    int quad = blockIdx.x;
    int tid  = threadIdx.x;

    for (int i = tid; i < 512; i += 256) {
        int g  = i >> 7;
        int lt = i & 127;
        const float4* rp = (const float4*)(sino + (size_t)(quad * 4 + g) * CC);
        float4 rv = rp[lt];
        int e0i = lt * 2;
        *(float2*)&sE[g][e0i]       = make_float2(rv.x, rv.z);
        *(float2*)&sE[g][e0i + 256] = make_float2(rv.x, rv.z);
        *(float2*)&sO[g][e0i]       = make_float2(rv.y, rv.w);
        *(float2*)&sO[g][e0i + 256] = make_float2(rv.y, rv.w);
    }
    {
        float s = sinf((float)(2 * tid + 1) * (float)(PI_D / 512.0));
        sh[tid] = -7.62939453125e-6f / (s * s);    // -(2/512^2)/sin^2
    }
    __syncthreads();

    int g  = tid >> 6;
    int p  = (tid >> 5) & 1;
    int q  = tid & 31;
    int o0 = q * 8;

    const float* part = p ? sE[g] : sO[g];
    const float* own  = p ? sO[g] : sE[g];

    float a0=0.f,a1=0.f,a2=0.f,a3=0.f,a4=0.f,a5=0.f,a6=0.f,a7=0.f;

    // two truncated ranges: [0,64) and [192,256); window re-seeded at each range start
    #pragma unroll 1
    for (int seg = 0; seg < 2; seg++) {
        int kbeg = seg ? 192 : 0;
        int kend = seg ? 256 : 64;
        float4 B4 = *(const float4*)&part[o0 - kbeg + 256];
        float4 C4 = *(const float4*)&part[o0 - kbeg + 260];
        if (p == 0) {
            #pragma unroll 4
            for (int k0 = kbeg; k0 < kend; k0 += 4) {
                float4 hv = *(const float4*)&sh[k0];
                float4 A4 = *(const float4*)&part[o0 - k0 + 252];
                a0 = fmaf(hv.x, A4.w, a0); a0 = fmaf(hv.y, A4.z, a0); a0 = fmaf(hv.z, A4.y, a0); a0 = fmaf(hv.w, A4.x, a0);
                a1 = fmaf(hv.x, B4.x, a1); a1 = fmaf(hv.y, A4.w, a1); a1 = fmaf(hv.z, A4.z, a1); a1 = fmaf(hv.w, A4.y, a1);
                a2 = fmaf(hv.x, B4.y, a2); a2 = fmaf(hv.y, B4.x, a2); a2 = fmaf(hv.z, A4.w, a2); a2 = fmaf(hv.w, A4.z, a2);
                a3 = fmaf(hv.x, B4.z, a3); a3 = fmaf(hv.y, B4.y, a3); a3 = fmaf(hv.z, B4.x, a3); a3 = fmaf(hv.w, A4.w, a3);
                a4 = fmaf(hv.x, B4.w, a4); a4 = fmaf(hv.y, B4.z, a4); a4 = fmaf(hv.z, B4.y, a4); a4 = fmaf(hv.w, B4.x, a4);
                a5 = fmaf(hv.x, C4.x, a5); a5 = fmaf(hv.y, B4.w, a5); a5 = fmaf(hv.z, B4.z, a5); a5 = fmaf(hv.w, B4.y, a5);
                a6 = fmaf(hv.x, C4.y, a6); a6 = fmaf(hv.y, C4.x, a6); a6 = fmaf(hv.z, B4.w, a6); a6 = fmaf(hv.w, B4.z, a6);
                a7 = fmaf(hv.x, C4.z, a7); a7 = fmaf(hv.y, C4.y, a7); a7 = fmaf(hv.z, C4.x, a7); a7 = fmaf(hv.w, B4.w, a7);
                C4 = B4; B4 = A4;
            }
        } else {
            #pragma unroll 4
            for (int k0 = kbeg; k0 < kend; k0 += 4) {
                float4 hv = *(const float4*)&sh[k0];
                float4 A4 = *(const float4*)&part[o0 - k0 + 252];
                a0 = fmaf(hv.x, B4.x, a0); a0 = fmaf(hv.y, A4.w, a0); a0 = fmaf(hv.z, A4.z, a0); a0 = fmaf(hv.w, A4.y, a0);
                a1 = fmaf(hv.x, B4.y, a1); a1 = fmaf(hv.y, B4.x, a1); a1 = fmaf(hv.z, A4.w, a1); a1 = fmaf(hv.w, A4.z, a1);
                a2 = fmaf(hv.x, B4.z, a2); a2 = fmaf(hv.y, B4.y, a2); a2 = fmaf(hv.z, B4.x, a2); a2 = fmaf(hv.w, A4.w, a2);
                a3 = fmaf(hv.x, B4.w, a3); a3 = fmaf(hv.y, B4.z, a3); a3 = fmaf(hv.z, B4.y, a3); a3 = fmaf(hv.w, B4.x, a3);
                a4 = fmaf(hv.x, C4.x, a4); a4 = fmaf(hv.y, B4.w, a4); a4 = fmaf(hv.z, B4.z, a4); a4 = fmaf(hv.w, B4.y, a4);
                a5 = fmaf(hv.x, C4.y, a5); a5 = fmaf(hv.y, C4.x, a5); a5 = fmaf(hv.z, B4.w, a5); a5 = fmaf(hv.w, B4.z, a5);
                a6 = fmaf(hv.x, C4.z, a6); a6 = fmaf(hv.y, C4.y, a6); a6 = fmaf(hv.z, C4.x, a6); a6 = fmaf(hv.w, B4.w, a6);
                a7 = fmaf(hv.x, C4.w, a7); a7 = fmaf(hv.y, C4.z, a7); a7 = fmaf(hv.z, C4.y, a7); a7 = fmaf(hv.w, C4.x, a7);
                C4 = B4; B4 = A4;
            }
        }
    }
    int ob = 2 * o0 + p;
    sF[g][ob + 0]  = fmaf(0.5f, own[o0 + 0], a0);
    sF[g][ob + 2]  = fmaf(0.5f, own[o0 + 1], a1);
    sF[g][ob + 4]  = fmaf(0.5f, own[o0 + 2], a2);
    sF[g][ob + 6]  = fmaf(0.5f, own[o0 + 3], a3);
    sF[g][ob + 8]  = fmaf(0.5f, own[o0 + 4], a4);
    sF[g][ob + 10] = fmaf(0.5f, own[o0 + 5], a5);
    sF[g][ob + 12] = fmaf(0.5f, own[o0 + 6], a6);
    sF[g][ob + 14] = fmaf(0.5f, own[o0 + 7], a7);
    __syncthreads();

    uint4* dst = g_quad + (size_t)quad * NPADE;
    for (int j = tid; j < NPADE; j += 256) {
        int ia = j - PADL;       ia = ia < 0 ? 0 : (ia > 511 ? 511 : ia);
        int ib = j - (PADL - 1); ib = ib < 0 ? 0 : (ib > 511 ? 511 : ib);
        float f0a = sF[0][ia], f0b = sF[0][ib];
        float f1a = sF[1][ia], f1b = sF[1][ib];
        float f2a = sF[2][ia], f2b = sF[2][ib];
        float f3a = sF[3][ia], f3b = sF[3][ib];
        __half2 m01 = __floats2half2_rn(0.5f * (f0a + f0b), 0.5f * (f1a + f1b));
        __half2 d01 = __floats2half2_rn(f0b - f0a, f1b - f1a);
        __half2 m23 = __floats2half2_rn(0.5f * (f2a + f2b), 0.5f * (f3a + f3b));
        __half2 d23 = __floats2half2_rn(f2b - f2a, f3b - f3a);
        uint4 e;
        e.x = *(unsigned int*)&m01; e.y = *(unsigned int*)&d01;
        e.z = *(unsigned int*)&m23; e.w = *(unsigned int*)&d23;
        dst[j] = e;
    }
}

// ---------------- cp.async helpers ------------------------------------------------------
__device__ __forceinline__ void cp16(unsigned int sdst, const void* gsrc) {
    asm volatile("cp.async.cg.shared.global [%0], [%1], 16;" :: "r"(sdst), "l"(gsrc));
}
__device__ __forceinline__ void cp_commit() { asm volatile("cp.async.commit_group;"); }
__device__ __forceinline__ void cp_wait1()  { asm volatile("cp.async.wait_group 1;"); }
__device__ __forceinline__ void cp_wait0()  { asm volatile("cp.async.wait_group 0;"); }

// ---------------- backprojection: mirror-angle sharing (best measured config, 481us) ----
// 1024 blocks x 512 threads. tid = jh*256 + xh: pixel pair (xh, 511-xh), 4 y's each.
// Groups g=0..88: rows v=g+1, vm=179-g. t_vm(x) = t_v(-x) -> 4 gathers share 2 t's.
__global__ void __launch_bounds__(512, 2) bp_kernel(float* __restrict__ out) {
    __shared__ __align__(16) uint4 sbuf[4][NPADE];   // 4 row buffers, 46.3KB
    __shared__ float2 scs[90];

    int tid  = threadIdx.x;
    int blk  = blockIdx.x;
    int slab = blk & 63;              // 64 slabs of 8 y
    int rq   = (blk >> 6) & 7;
    int b    = blk >> 9;

    if (tid < 90) {
        float th = (float)((double)tid * (PI_D / (double)VV));
        float s, c;
        sincosf(th, &s, &c);
        scs[tid] = make_float2(c, s);
    }

    int xh = tid & 255;
    int jh = tid >> 8;

    unsigned int sb32;
    asm("{ .reg .u64 t; cvta.to.shared.u64 t, %1; cvt.u32.u64 %0, t; }"
        : "=r"(sb32) : "l"((void*)&sbuf[0][0]));
    unsigned int cb = sb32 - 0xB4000000u;    // gather: addr = bits(ts)*16 + cb + buf*BUFB

    const size_t rstr = (size_t)8 * NPADE;   // uint4 per row step
    const uint4* gq = g_quad + ((size_t)(b * VV) * 8 + rq) * NPADE;

    auto stage = [&](int rA, int rB, int p) {
        const uint4* sA = gq + (size_t)rA * rstr;
        const uint4* sB = gq + (size_t)rB * rstr;
        unsigned int dA = sb32 + (unsigned int)(2 * p) * BUFB;
        unsigned int dB = dA + BUFB;
        cp16(dA + tid * 16u, sA + tid);
        if (tid < 212) cp16(dA + (tid + 512) * 16u, sA + tid + 512);
        else           cp16(dB + (tid - 212) * 16u, sB + (tid - 212));
        if (tid < 424) cp16(dB + (tid + 300) * 16u, sB + tid + 300);
    };

    // prologue: group0 (rows 1,179) -> pair0 ; group1 (rows 2,178) -> pair1
    stage(1, 179, 0); cp_commit();
    stage(2, 178, 1); cp_commit();

    float xp = (float)xh - 255.5f;
    float yb = (float)(slab * 8 + jh * 4) - 255.5f;

    float accA[4][4], accB[4][4];     // [r][j]
    #pragma unroll
    for (int r = 0; r < 4; r++)
        #pragma unroll
        for (int j = 0; j < 4; j++) { accA[r][j] = 0.f; accB[r][j] = 0.f; }

    __half2 hA01[4], hA23[4], hB01[4], hB23[4];
    #pragma unroll
    for (int j = 0; j < 4; j++) {
        hA01[j] = __float2half2_rn(0.f); hA23[j] = __float2half2_rn(0.f);
        hB01[j] = __float2half2_rn(0.f); hB23[j] = __float2half2_rn(0.f);
    }

    for (int g = 0; g < 89; g++) {
        cp_wait1();
        __syncthreads();

        int p = g & 1;
        unsigned int cbV = cb + (unsigned int)(2 * p) * BUFB;
        float2 cs = scs[g + 1];
        float u   = xp * cs.x;
        float w00 = fmaf(yb, cs.y, KCONST);
        float tA0 = __fadd_rn(w00, u);
        float tB0 = __fadd_rn(w00, -u);

        #pragma unroll
        for (int j = 0; j < 4; j++) {
            float tA = fmaf((float)j, cs.y, tA0);
            float tB = fmaf((float)j, cs.y, tB0);
            float tsA  = __fadd_rn(tA, MAGICF);
            float i0A  = __fadd_rn(tsA, -MAGICF);
            float wA   = __fadd_rn(tA, -i0A);
            float tsB  = __fadd_rn(tB, MAGICF);
            float i0B  = __fadd_rn(tsB, -MAGICF);
            float wB   = __fadd_rn(tB, -i0B);
            unsigned int uA = __float_as_uint(tsA) * 16u + cbV;
            unsigned int uB = __float_as_uint(tsB) * 16u + cbV;
            unsigned int wAb, wBb;
            asm("cvt.rn.f16x2.f32 %0, %1, %1;" : "=r"(wAb) : "f"(wA));
            asm("cvt.rn.f16x2.f32 %0, %1, %1;" : "=r"(wBb) : "f"(wB));
            __half2 wA2 = *(__half2*)&wAb, wB2 = *(__half2*)&wBb;

            unsigned int x0, x1, x2, x3;
            asm("ld.shared.v4.b32 {%0,%1,%2,%3}, [%4];"
                : "=r"(x0), "=r"(x1), "=r"(x2), "=r"(x3) : "r"(uA));
            hA01[j] = __hadd2(hA01[j], __hfma2(wA2, *(__half2*)&x1, *(__half2*)&x0));
            hA23[j] = __hadd2(hA23[j], __hfma2(wA2, *(__half2*)&x3, *(__half2*)&x2));
            asm("ld.shared.v4.b32 {%0,%1,%2,%3}, [%4];"
                : "=r"(x0), "=r"(x1), "=r"(x2), "=r"(x3) : "r"(uB));
            hB01[j] = __hadd2(hB01[j], __hfma2(wB2, *(__half2*)&x1, *(__half2*)&x0));
            hB23[j] = __hadd2(hB23[j], __hfma2(wB2, *(__half2*)&x3, *(__half2*)&x2));
            asm("ld.shared.v4.b32 {%0,%1,%2,%3}, [%4+11584];"
                : "=r"(x0), "=r"(x1), "=r"(x2), "=r"(x3) : "r"(uB));
            hA01[j] = __hadd2(hA01[j], __hfma2(wB2, *(__half2*)&x1, *(__half2*)&x0));
            hA23[j] = __hadd2(hA23[j], __hfma2(wB2, *(__half2*)&x3, *(__half2*)&x2));
            asm("ld.shared.v4.b32 {%0,%1,%2,%3}, [%4+11584];"
                : "=r"(x0), "=r"(x1), "=r"(x2), "=r"(x3) : "r"(uA));
            hB01[j] = __hadd2(hB01[j], __hfma2(wA2, *(__half2*)&x1, *(__half2*)&x0));
            hB23[j] = __hadd2(hB23[j], __hfma2(wA2, *(__half2*)&x3, *(__half2*)&x2));
        }

        __syncthreads();
        if (g + 2 <= 88)      stage(g + 3, 177 - g, p);
        else if (g + 2 == 89) stage(0, 90, p);
        cp_commit();

        if ((g & 3) == 3) {
            #pragma unroll
            for (int j = 0; j < 4; j++) {
                accA[0][j] += __low2float(hA01[j]);  accA[1][j] += __high2float(hA01[j]);
                accA[2][j] += __low2float(hA23[j]);  accA[3][j] += __high2float(hA23[j]);
                accB[0][j] += __low2float(hB01[j]);  accB[1][j] += __high2float(hB01[j]);
                accB[2][j] += __low2float(hB23[j]);  accB[3][j] += __high2float(hB23[j]);
                hA01[j] = __float2half2_rn(0.f); hA23[j] = __float2half2_rn(0.f);
                hB01[j] = __float2half2_rn(0.f); hB23[j] = __float2half2_rn(0.f);
            }
        }
    }

    // epilogue: specials row0 (buf2) and row90 (buf3) -- staged into pair 1
    cp_wait0();
    __syncthreads();
    {
        unsigned int cb0  = cb + 2u * BUFB;
        {
            float tA = __fadd_rn(KCONST, xp);
            float tsA = __fadd_rn(tA, MAGICF);
            float wA  = __fadd_rn(tA, -__fadd_rn(tsA, -MAGICF));
            float tB = __fadd_rn(KCONST, -xp);
            float tsB = __fadd_rn(tB, MAGICF);
            float wB  = __fadd_rn(tB, -__fadd_rn(tsB, -MAGICF));
            unsigned int wAb, wBb;
            asm("cvt.rn.f16x2.f32 %0, %1, %1;" : "=r"(wAb) : "f"(wA));
            asm("cvt.rn.f16x2.f32 %0, %1, %1;" : "=r"(wBb) : "f"(wB));
            unsigned int x0, x1, x2, x3;
            asm("ld.shared.v4.b32 {%0,%1,%2,%3}, [%4];"
                : "=r"(x0), "=r"(x1), "=r"(x2), "=r"(x3) : "r"(__float_as_uint(tsA) * 16u + cb0));
            __half2 vA01 = __hfma2(*(__half2*)&wAb, *(__half2*)&x1, *(__half2*)&x0);
            __half2 vA23 = __hfma2(*(__half2*)&wAb, *(__half2*)&x3, *(__half2*)&x2);
            asm("ld.shared.v4.b32 {%0,%1,%2,%3}, [%4];"
                : "=r"(x0), "=r"(x1), "=r"(x2), "=r"(x3) : "r"(__float_as_uint(tsB) * 16u + cb0));
            __half2 vB01 = __hfma2(*(__half2*)&wBb, *(__half2*)&x1, *(__half2*)&x0);
            __half2 vB23 = __hfma2(*(__half2*)&wBb, *(__half2*)&x3, *(__half2*)&x2);
            #pragma unroll
            for (int j = 0; j < 4; j++) {
                hA01[j] = __hadd2(hA01[j], vA01); hA23[j] = __hadd2(hA23[j], vA23);
                hB01[j] = __hadd2(hB01[j], vB01); hB23[j] = __hadd2(hB23[j], vB23);
            }
        }
        #pragma unroll
        for (int j = 0; j < 4; j++) {
            float t  = __fadd_rn(__fadd_rn(yb, (float)j), KCONST);
            float ts = __fadd_rn(t, MAGICF);
            float w  = __fadd_rn(t, -__fadd_rn(ts, -MAGICF));
            unsigned int wb;
            asm("cvt.rn.f16x2.f32 %0, %1, %1;" : "=r"(wb) : "f"(w));
            unsigned int x0, x1, x2, x3;
            asm("ld.shared.v4.b32 {%0,%1,%2,%3}, [%4+11584];"
                : "=r"(x0), "=r"(x1), "=r"(x2), "=r"(x3) : "r"(__float_as_uint(ts) * 16u + cb0));
            __half2 v01 = __hfma2(*(__half2*)&wb, *(__half2*)&x1, *(__half2*)&x0);
            __half2 v23 = __hfma2(*(__half2*)&wb, *(__half2*)&x3, *(__half2*)&x2);
            hA01[j] = __hadd2(hA01[j], v01); hA23[j] = __hadd2(hA23[j], v23);
            hB01[j] = __hadd2(hB01[j], v01); hB23[j] = __hadd2(hB23[j], v23);
        }
        #pragma unroll
        for (int j = 0; j < 4; j++) {
            accA[0][j] += __low2float(hA01[j]);  accA[1][j] += __high2float(hA01[j]);
            accA[2][j] += __low2float(hA23[j]);  accA[3][j] += __high2float(hA23[j]);
            accB[0][j] += __low2float(hB01[j]);  accB[1][j] += __high2float(hB01[j]);
            accB[2][j] += __low2float(hB23[j]);  accB[3][j] += __high2float(hB23[j]);
        }
    }

    const float scale = (float)(PI_D / (double)VV);
    int y0 = slab * 8 + jh * 4;
    #pragma unroll
    for (int r = 0; r < 4; r++) {
        size_t obase = (((size_t)(b * RR + rq * 4 + r)) * NPIX + y0) * NPIX;
        #pragma unroll
        for (int j = 0; j < 4; j++) {
            float vA = accA[r][j] * scale;
            float vB = accB[r][j] * scale;
            out[obase + (size_t)j * NPIX + xh]         = vA > 0.f ? vA : 0.f;
            out[obase + (size_t)j * NPIX + (511 - xh)] = vB > 0.f ? vB : 0.f;
        }
    }
}

// ---------------- launch ----------------------------------------------------------------
extern "C" void kernel_launch(void* const* d_in, const int* in_sizes, int n_in,
                              void* d_out, int out_size) {
    const float* sino = (const float*)d_in[0];
    float* out = (float*)d_out;
    (void)in_sizes; (void)n_in; (void)out_size;

    filter_kernel<<<NQUADS, 256>>>(sino);
    bp_kernel<<<BB * (RR / 4) * (NPIX / 8), 512>>>(out);
}